// round 8
// baseline (speedup 1.0000x reference)
#include <cuda_runtime.h>
#include <math_constants.h>

#define BB 64
#define CC 256
#define HW 4096
#define CS 64
#define NC 8

// ---- scratch (no allocations allowed) ----
__device__ float g_mean[BB * CC];
__device__ float g_min[BB * CC];
__device__ float g_max[BB * CC];
__device__ float g_scale[BB * CC];
__device__ float g_smin[BB];
__device__ float g_smax[BB];
__device__ float g_s[BB];
__device__ float g_z[BB];

// ------------------------------------------------------------------
// Kernel 1: per-(b,c) mean / min / max. ONE WARP per channel:
// 32 lanes x 32 float4 = 4096 floats, fully unrolled loads (high MLP),
// then warp-shuffle reduce only. No smem, no syncthreads.
// ------------------------------------------------------------------
__global__ void __launch_bounds__(256) k_stat(const float* __restrict__ x) {
    int gw   = (blockIdx.x * blockDim.x + threadIdx.x) >> 5;  // global warp = (b,c)
    int lane = threadIdx.x & 31;
    const float4* xp = reinterpret_cast<const float4*>(x) + (size_t)gw * (HW / 4) + lane;

    float s0 = 0.f, s1 = 0.f, s2 = 0.f, s3 = 0.f;
    float mn = CUDART_INF_F, mx = -CUDART_INF_F;
#pragma unroll
    for (int i = 0; i < 8; i++) {
        float4 a = __ldcs(xp + (i * 4 + 0) * 32);
        float4 b = __ldcs(xp + (i * 4 + 1) * 32);
        float4 c = __ldcs(xp + (i * 4 + 2) * 32);
        float4 d = __ldcs(xp + (i * 4 + 3) * 32);
        s0 += (a.x + a.y) + (a.z + a.w);
        s1 += (b.x + b.y) + (b.z + b.w);
        s2 += (c.x + c.y) + (c.z + c.w);
        s3 += (d.x + d.y) + (d.z + d.w);
        mn = fminf(mn, fminf(fminf(a.x, a.y), fminf(a.z, a.w)));
        mn = fminf(mn, fminf(fminf(b.x, b.y), fminf(b.z, b.w)));
        mn = fminf(mn, fminf(fminf(c.x, c.y), fminf(c.z, c.w)));
        mn = fminf(mn, fminf(fminf(d.x, d.y), fminf(d.z, d.w)));
        mx = fmaxf(mx, fmaxf(fmaxf(a.x, a.y), fmaxf(a.z, a.w)));
        mx = fmaxf(mx, fmaxf(fmaxf(b.x, b.y), fmaxf(b.z, b.w)));
        mx = fmaxf(mx, fmaxf(fmaxf(c.x, c.y), fmaxf(c.z, c.w)));
        mx = fmaxf(mx, fmaxf(fmaxf(d.x, d.y), fmaxf(d.z, d.w)));
    }
    float s = (s0 + s1) + (s2 + s3);
#pragma unroll
    for (int o = 16; o > 0; o >>= 1) {
        s  += __shfl_down_sync(0xffffffffu, s, o);
        mn = fminf(mn, __shfl_down_sync(0xffffffffu, mn, o));
        mx = fmaxf(mx, __shfl_down_sync(0xffffffffu, mx, o));
    }
    if (lane == 0) {
        g_mean[gw] = s * (1.0f / HW);
        g_min[gw]  = mn;
        g_max[gw]  = mx;
    }
}

// ------------------------------------------------------------------
// Kernel 2: SE MLP + hardsigmoid scale per (b,c), and per-sample
// min/max of out = scale*x (scale>=0 => min(scale*x)=scale*min(x)).
// One block per batch sample, 256 threads (= C).
// ------------------------------------------------------------------
__global__ void k_se(const float* __restrict__ w1, const float* __restrict__ b1,
                     const float* __restrict__ w2, const float* __restrict__ b2) {
    int b = blockIdx.x, t = threadIdx.x;
    __shared__ float pooled[CC];
    __shared__ float hsh[CS];

    pooled[t] = g_mean[b * CC + t];
    __syncthreads();

    if (t < CS) {
        float acc = b1[t];
#pragma unroll 8
        for (int c = 0; c < CC; c++) acc = fmaf(pooled[c], w1[t * CC + c], acc);
        hsh[t] = fmaxf(acc, 0.f);
    }
    __syncthreads();

    float acc = b2[t];
#pragma unroll 8
    for (int s = 0; s < CS; s++) acc = fmaf(hsh[s], w2[t * CS + s], acc);
    float sc = fminf(fmaxf(acc / 6.0f + 0.5f, 0.f), 1.f);   // hardsigmoid
    g_scale[b * CC + t] = sc;

    float mn = sc * g_min[b * CC + t];
    float mx = sc * g_max[b * CC + t];
#pragma unroll
    for (int o = 16; o > 0; o >>= 1) {
        mn = fminf(mn, __shfl_down_sync(0xffffffffu, mn, o));
        mx = fmaxf(mx, __shfl_down_sync(0xffffffffu, mx, o));
    }
    __shared__ float sh_mn[8], sh_mx[8];
    int w = t >> 5, l = t & 31;
    if (l == 0) { sh_mn[w] = mn; sh_mx[w] = mx; }
    __syncthreads();
    if (t == 0) {
        float MN = CUDART_INF_F, MX = -CUDART_INF_F;
#pragma unroll
        for (int i = 0; i < 8; i++) { MN = fminf(MN, sh_mn[i]); MX = fmaxf(MX, sh_mx[i]); }
        g_smin[b] = MN;
        g_smax[b] = MX;
    }
}

// ------------------------------------------------------------------
// Kernel 3: per-cluster segment min/max, EMA range update, quant params,
// scattered back to per-sample s/z. One block.
// ------------------------------------------------------------------
__global__ void k_cluster(const float* __restrict__ act_range,
                          const int* __restrict__ scl) {
    __shared__ float cs[NC], cz[NC];
    int t = threadIdx.x;
    if (t < NC) {
        float mn = CUDART_INF_F, mx = -CUDART_INF_F;  // JAX segment_min/max identities
        for (int b = 0; b < BB; b++) {
            if (scl[b] == t) {
                mn = fminf(mn, g_smin[b]);
                mx = fmaxf(mx, g_smax[b]);
            }
        }
        float nm = act_range[t * 2 + 0] * 0.995f + mn * 0.005f;
        float nx = act_range[t * 2 + 1] * 0.995f + mx * 0.005f;
        float s = (nx - nm) / 255.0f;
        float z = -rintf(__fdiv_rn(nm, s));
        cs[t] = s;
        cz[t] = z;
    }
    __syncthreads();
    if (t < BB) {
        int k = scl[t];
        g_s[t] = cs[k];
        g_z[t] = cz[k];
    }
}

// ------------------------------------------------------------------
// Kernel 4: streaming fake-quant. Each block covers 4 consecutive
// channels with 1024 threads: thread t handles float4 offset t of
// each of the 4 channels (full coverage: 1024 x 4 = 4096 float4).
// Loads front-batched (MLP_p1=4), streaming cache hints.
// ------------------------------------------------------------------
__global__ void __launch_bounds__(1024) k_quant(const float* __restrict__ x,
                                                float* __restrict__ out) {
    int t  = threadIdx.x;               // [0, 1024) = full channel in float4
    int cb = blockIdx.x * 4;            // first channel of this block
    int bs = blockIdx.x >> 6;           // batch sample (256 ch / 4 per block)
    float s = __ldg(&g_s[bs]);
    float z = __ldg(&g_z[bs]);

    size_t base = (size_t)blockIdx.x * 4096 + t;
    const float4* xp = reinterpret_cast<const float4*>(x) + base;
    float4*       op = reinterpret_cast<float4*>(out) + base;

    float4 v[4];
    float  sc[4];
#pragma unroll
    for (int k = 0; k < 4; k++) {
        v[k]  = __ldcs(xp + k * (HW / 4));
        sc[k] = __ldg(&g_scale[cb + k]);
    }
#pragma unroll
    for (int k = 0; k < 4; k++) {
        float4 r;
#define QUANT(a, o)                                                            \
        {                                                                      \
            float ov = sc[k] * (a);                                            \
            float q  = fminf(fmaxf(rintf(__fdiv_rn(ov, s) + z), 0.f), 255.f);  \
            (o) = (q - z) * s;                                                 \
        }
        QUANT(v[k].x, r.x)
        QUANT(v[k].y, r.y)
        QUANT(v[k].z, r.z)
        QUANT(v[k].w, r.w)
#undef QUANT
        __stcs(op + k * (HW / 4), r);
    }
}

extern "C" void kernel_launch(void* const* d_in, const int* in_sizes, int n_in,
                              void* d_out, int out_size) {
    const float* x         = (const float*)d_in[0];
    const float* w1        = (const float*)d_in[1];
    const float* b1        = (const float*)d_in[2];
    const float* w2        = (const float*)d_in[3];
    const float* b2        = (const float*)d_in[4];
    const float* act_range = (const float*)d_in[5];
    const int*   scl       = (const int*)d_in[6];
    float* out = (float*)d_out;

    // k_stat: one warp per (b,c) channel -> 16384 warps, 8 warps/block
    k_stat<<<(BB * CC) / 8, 256>>>(x);
    k_se<<<BB, 256>>>(w1, b1, w2, b2);
    k_cluster<<<1, 64>>>(act_range, scl);
    // k_quant: 4 channels per 1024-thread block (full coverage)
    k_quant<<<(BB * CC) / 4, 1024>>>(x, out);
}

// round 9
// speedup vs baseline: 1.2761x; 1.2761x over previous
#include <cuda_runtime.h>
#include <math_constants.h>

#define BB 64
#define CC 256
#define HW 4096
#define CS 64
#define NC 8

// ---- scratch (no allocations allowed) ----
__device__ float g_mean[BB * CC];
__device__ float g_min[BB * CC];
__device__ float g_max[BB * CC];
__device__ float g_scale[BB * CC];
__device__ float g_smin[BB];
__device__ float g_smax[BB];
__device__ float g_s[BB];
__device__ float g_z[BB];

// ------------------------------------------------------------------
// Kernel 1: per-(b,c) mean / min / max. One WARP per channel
// (tail = 15 SHFLs amortized over 128 loads), but load loop kept at
// unroll 1 so each batch is only 4 LDG.128 (MLP_p1~4 -> low cross-CTA
// L1tex-queue spread per the B300 model).
// ------------------------------------------------------------------
__global__ void __launch_bounds__(256) k_stat(const float* __restrict__ x) {
    int gw   = (blockIdx.x * blockDim.x + threadIdx.x) >> 5;  // global warp = (b,c)
    int lane = threadIdx.x & 31;
    const float4* xp = reinterpret_cast<const float4*>(x) + (size_t)gw * (HW / 4) + lane;

    float s0 = 0.f, s1 = 0.f, s2 = 0.f, s3 = 0.f;
    float mn = CUDART_INF_F, mx = -CUDART_INF_F;
#pragma unroll 1
    for (int i = 0; i < 8; i++) {
        const float4* p = xp + i * 128;
        float4 a = __ldg(p);
        float4 b = __ldg(p + 32);
        float4 c = __ldg(p + 64);
        float4 d = __ldg(p + 96);
        s0 += (a.x + a.y) + (a.z + a.w);
        s1 += (b.x + b.y) + (b.z + b.w);
        s2 += (c.x + c.y) + (c.z + c.w);
        s3 += (d.x + d.y) + (d.z + d.w);
        mn = fminf(mn, fminf(fminf(a.x, a.y), fminf(a.z, a.w)));
        mn = fminf(mn, fminf(fminf(b.x, b.y), fminf(b.z, b.w)));
        mn = fminf(mn, fminf(fminf(c.x, c.y), fminf(c.z, c.w)));
        mn = fminf(mn, fminf(fminf(d.x, d.y), fminf(d.z, d.w)));
        mx = fmaxf(mx, fmaxf(fmaxf(a.x, a.y), fmaxf(a.z, a.w)));
        mx = fmaxf(mx, fmaxf(fmaxf(b.x, b.y), fmaxf(b.z, b.w)));
        mx = fmaxf(mx, fmaxf(fmaxf(c.x, c.y), fmaxf(c.z, c.w)));
        mx = fmaxf(mx, fmaxf(fmaxf(d.x, d.y), fmaxf(d.z, d.w)));
    }
    float s = (s0 + s1) + (s2 + s3);
#pragma unroll
    for (int o = 16; o > 0; o >>= 1) {
        s  += __shfl_down_sync(0xffffffffu, s, o);
        mn = fminf(mn, __shfl_down_sync(0xffffffffu, mn, o));
        mx = fmaxf(mx, __shfl_down_sync(0xffffffffu, mx, o));
    }
    if (lane == 0) {
        g_mean[gw] = s * (1.0f / HW);
        g_min[gw]  = mn;
        g_max[gw]  = mx;
    }
}

// ------------------------------------------------------------------
// Kernel 2: SE MLP + hardsigmoid scale per (b,c), and per-sample
// min/max of out = scale*x (scale>=0 => min(scale*x)=scale*min(x)).
// One block per batch sample, 256 threads (= C).
// ------------------------------------------------------------------
__global__ void k_se(const float* __restrict__ w1, const float* __restrict__ b1,
                     const float* __restrict__ w2, const float* __restrict__ b2) {
    int b = blockIdx.x, t = threadIdx.x;
    __shared__ float pooled[CC];
    __shared__ float hsh[CS];

    pooled[t] = g_mean[b * CC + t];
    __syncthreads();

    if (t < CS) {
        float acc = b1[t];
#pragma unroll 8
        for (int c = 0; c < CC; c++) acc = fmaf(pooled[c], w1[t * CC + c], acc);
        hsh[t] = fmaxf(acc, 0.f);
    }
    __syncthreads();

    float acc = b2[t];
#pragma unroll 8
    for (int s = 0; s < CS; s++) acc = fmaf(hsh[s], w2[t * CS + s], acc);
    float sc = fminf(fmaxf(acc / 6.0f + 0.5f, 0.f), 1.f);   // hardsigmoid
    g_scale[b * CC + t] = sc;

    float mn = sc * g_min[b * CC + t];
    float mx = sc * g_max[b * CC + t];
#pragma unroll
    for (int o = 16; o > 0; o >>= 1) {
        mn = fminf(mn, __shfl_down_sync(0xffffffffu, mn, o));
        mx = fmaxf(mx, __shfl_down_sync(0xffffffffu, mx, o));
    }
    __shared__ float sh_mn[8], sh_mx[8];
    int w = t >> 5, l = t & 31;
    if (l == 0) { sh_mn[w] = mn; sh_mx[w] = mx; }
    __syncthreads();
    if (t == 0) {
        float MN = CUDART_INF_F, MX = -CUDART_INF_F;
#pragma unroll
        for (int i = 0; i < 8; i++) { MN = fminf(MN, sh_mn[i]); MX = fmaxf(MX, sh_mx[i]); }
        g_smin[b] = MN;
        g_smax[b] = MX;
    }
}

// ------------------------------------------------------------------
// Kernel 3: per-cluster segment min/max, EMA range update, quant params,
// scattered back to per-sample s/z. One block.
// ------------------------------------------------------------------
__global__ void k_cluster(const float* __restrict__ act_range,
                          const int* __restrict__ scl) {
    __shared__ float cs[NC], cz[NC];
    int t = threadIdx.x;
    if (t < NC) {
        float mn = CUDART_INF_F, mx = -CUDART_INF_F;  // JAX segment_min/max identities
        for (int b = 0; b < BB; b++) {
            if (scl[b] == t) {
                mn = fminf(mn, g_smin[b]);
                mx = fmaxf(mx, g_smax[b]);
            }
        }
        float nm = act_range[t * 2 + 0] * 0.995f + mn * 0.005f;
        float nx = act_range[t * 2 + 1] * 0.995f + mx * 0.005f;
        float s = (nx - nm) / 255.0f;
        float z = -rintf(__fdiv_rn(nm, s));
        cs[t] = s;
        cz[t] = z;
    }
    __syncthreads();
    if (t < BB) {
        int k = scl[t];
        g_s[t] = cs[k];
        g_z[t] = cz[k];
    }
}

// ------------------------------------------------------------------
// Kernel 4: streaming fake-quant — EXACT R2 config (measured 84 us,
// 73.9% DRAM, occ 78.5%, regs 21). One float4 per thread.
// ------------------------------------------------------------------
__global__ void __launch_bounds__(256) k_quant(const float* __restrict__ x,
                                               float* __restrict__ out) {
    int i = blockIdx.x * blockDim.x + threadIdx.x;  // float4 index
    int bc = i >> 10;        // HW/4 = 1024 float4 per channel
    int b  = bc >> 8;        // CC = 256 channels per sample
    float sc = __ldg(&g_scale[bc]);
    float s  = __ldg(&g_s[b]);
    float z  = __ldg(&g_z[b]);

    float4 v = reinterpret_cast<const float4*>(x)[i];
    float4 r;
#define QUANT(a, o)                                                          \
    {                                                                        \
        float ov = sc * (a);                                                 \
        float q  = fminf(fmaxf(rintf(__fdiv_rn(ov, s) + z), 0.f), 255.f);    \
        (o) = (q - z) * s;                                                   \
    }
    QUANT(v.x, r.x)
    QUANT(v.y, r.y)
    QUANT(v.z, r.z)
    QUANT(v.w, r.w)
#undef QUANT
    reinterpret_cast<float4*>(out)[i] = r;
}

extern "C" void kernel_launch(void* const* d_in, const int* in_sizes, int n_in,
                              void* d_out, int out_size) {
    const float* x         = (const float*)d_in[0];
    const float* w1        = (const float*)d_in[1];
    const float* b1        = (const float*)d_in[2];
    const float* w2        = (const float*)d_in[3];
    const float* b2        = (const float*)d_in[4];
    const float* act_range = (const float*)d_in[5];
    const int*   scl       = (const int*)d_in[6];
    float* out = (float*)d_out;

    // k_stat: one warp per (b,c) channel, 8 warps/block, batches of 4 loads
    k_stat<<<(BB * CC) / 8, 256>>>(x);
    k_se<<<BB, 256>>>(w1, b1, w2, b2);
    k_cluster<<<1, 64>>>(act_range, scl);
    // k_quant: R2 config — 1 float4/thread, 65536 blocks
    k_quant<<<(BB * CC * HW / 4) / 256, 256>>>(x, out);
}